// round 5
// baseline (speedup 1.0000x reference)
#include <cuda_runtime.h>
#include <cuda_fp16.h>
#include <cstdint>

// ---------------------------------------------------------------------------
// Problem constants
// ---------------------------------------------------------------------------
#define B_   16
#define H_   64
#define W_   64
#define C_   256
#define KE   4
#define F_   256
#define HW_  (H_ * W_)
#define KTOT 2304
#define PER_E (9 * C_ * F_)

// GEMM tiling
#define BM 128
#define BN 128
#define BK 32
#define NITER 72
#define STAGES 4
#define A_ROW_BYTES 80               // 64B data + 16B pad (conflict-free ldmatrix)
#define A_STAGE (BM * A_ROW_BYTES)   // 10240
#define B_STAGE (BK * BN * 2)        // 8192
#define STG_BYTES (A_STAGE + B_STAGE)
#define SMEM_TOTAL (STAGES * STG_BYTES)   // 73728

// ---------------------------------------------------------------------------
// Device scratch
// ---------------------------------------------------------------------------
__device__ float g_partial[B_ * 16 * C_];
__device__ float g_att[B_ * KE];
__device__ float g_bias[B_ * F_];
__device__ __align__(16) __half g_in_h[B_ * HW_ * C_];
__device__ __align__(16) __half g_w[B_ * KTOT * F_];

// ---------------------------------------------------------------------------
// PTX helpers
// ---------------------------------------------------------------------------
__device__ __forceinline__ uint32_t smem_u32(const void* p) {
    uint32_t a;
    asm("{ .reg .u64 t; cvta.to.shared.u64 t, %1; cvt.u32.u64 %0, t; }" : "=r"(a) : "l"(p));
    return a;
}
#define CP_ASYNC16(dst, src, ok) \
    asm volatile("{\n\t.reg .pred p;\n\t.reg .b32 sz;\n\tsetp.ne.u32 p, %2, 0;\n\tselp.b32 sz, 16, 0, p;\n\tcp.async.cg.shared.global [%0], [%1], 16, sz;\n\t}" \
        :: "r"(dst), "l"(src), "r"((unsigned)(ok)) : "memory")
#define CP_COMMIT() asm volatile("cp.async.commit_group;" ::: "memory")
#define CP_WAIT2()  asm volatile("cp.async.wait_group 2;" ::: "memory")

#define LDSM_X4(r0, r1, r2, r3, a) \
    asm volatile("ldmatrix.sync.aligned.m8n8.x4.shared.b16 {%0,%1,%2,%3}, [%4];" \
        : "=r"(r0), "=r"(r1), "=r"(r2), "=r"(r3) : "r"(a))
#define LDSM_X4_T(r0, r1, r2, r3, a) \
    asm volatile("ldmatrix.sync.aligned.m8n8.x4.trans.shared.b16 {%0,%1,%2,%3}, [%4];" \
        : "=r"(r0), "=r"(r1), "=r"(r2), "=r"(r3) : "r"(a))

#define MMA16816(c0, c1, c2, c3, a0, a1, a2, a3, b0, b1) \
    asm volatile("mma.sync.aligned.m16n8k16.row.col.f32.f16.f16.f32 " \
        "{%0,%1,%2,%3}, {%4,%5,%6,%7}, {%8,%9}, {%0,%1,%2,%3};" \
        : "+f"(c0), "+f"(c1), "+f"(c2), "+f"(c3) \
        : "r"(a0), "r"(a1), "r"(a2), "r"(a3), "r"(b0), "r"(b1))

// ---------------------------------------------------------------------------
// 1) Partial pooling
// ---------------------------------------------------------------------------
__global__ void pool_kernel(const float* __restrict__ in) {
    int b = blockIdx.y, s = blockIdx.x, c = threadIdx.x;
    const float* p = in + ((long)b * HW_ + s * 256) * C_ + c;
    float sum = 0.f;
#pragma unroll 4
    for (int i = 0; i < 256; i++) sum += p[i * C_];
    g_partial[(b * 16 + s) * C_ + c] = sum;
}

// ---------------------------------------------------------------------------
// 2) Routing
// ---------------------------------------------------------------------------
__global__ void route_kernel(const float* __restrict__ w1, const float* __restrict__ b1,
                             const float* __restrict__ w2, const float* __restrict__ b2,
                             const float* __restrict__ biases) {
    __shared__ float pool[C_];
    __shared__ float a1[64];
    __shared__ float att[KE];
    int b = blockIdx.x, t = threadIdx.x;

    float sum = 0.f;
#pragma unroll
    for (int s = 0; s < 16; s++) sum += g_partial[(b * 16 + s) * C_ + t];
    pool[t] = sum * (1.0f / (float)HW_);
    __syncthreads();

    if (t < 64) {
        float v = b1[t];
#pragma unroll 4
        for (int c = 0; c < C_; c++) v += pool[c] * w1[c * 64 + t];
        a1[t] = fmaxf(v, 0.f);
    }
    __syncthreads();
    if (t < KE) {
        float v = b2[t];
#pragma unroll
        for (int j = 0; j < 64; j++) v += a1[j] * w2[j * KE + t];
        att[t] = v;
    }
    __syncthreads();
    if (t == 0) {
        float m = att[0];
        for (int e = 1; e < KE; e++) m = fmaxf(m, att[e]);
        float ex[KE], s2 = 0.f;
        for (int e = 0; e < KE; e++) { ex[e] = expf(att[e] - m); s2 += ex[e]; }
        float inv = 1.0f / s2;
        for (int e = 0; e < KE; e++) { att[e] = ex[e] * inv; g_att[b * KE + e] = att[e]; }
    }
    __syncthreads();
    float bv = 0.f;
#pragma unroll
    for (int e = 0; e < KE; e++) bv += att[e] * biases[e * F_ + t];
    g_bias[b * F_ + t] = bv;
}

// ---------------------------------------------------------------------------
// 3) Convert inputs to fp16
// ---------------------------------------------------------------------------
__global__ void tohalf_kernel(const float* __restrict__ in) {
    long i = ((long)blockIdx.x * blockDim.x + threadIdx.x) * 8;
    float4 v0 = *(const float4*)(in + i);
    float4 v1 = *(const float4*)(in + i + 4);
    __half2 h[4];
    h[0] = __floats2half2_rn(v0.x, v0.y);
    h[1] = __floats2half2_rn(v0.z, v0.w);
    h[2] = __floats2half2_rn(v1.x, v1.y);
    h[3] = __floats2half2_rn(v1.z, v1.w);
    *(uint4*)(g_in_h + i) = *(uint4*)h;
}

// ---------------------------------------------------------------------------
// 4) Combine experts -> fp16 [b][k][f]. One pass over expert kernels, all b.
// ---------------------------------------------------------------------------
__global__ void combine_h_kernel(const float* __restrict__ kernels) {
    __shared__ float satt[B_ * KE];
    int t = threadIdx.x;
    if (t < B_ * KE) satt[t] = g_att[t];
    __syncthreads();

    long off = ((long)blockIdx.x * blockDim.x + t) * 4;
    float4 k0 = *(const float4*)(kernels + 0L * PER_E + off);
    float4 k1 = *(const float4*)(kernels + 1L * PER_E + off);
    float4 k2 = *(const float4*)(kernels + 2L * PER_E + off);
    float4 k3 = *(const float4*)(kernels + 3L * PER_E + off);

#pragma unroll
    for (int b = 0; b < B_; b++) {
        float a0 = satt[b * KE + 0], a1v = satt[b * KE + 1];
        float a2 = satt[b * KE + 2], a3 = satt[b * KE + 3];
        float rx = a0 * k0.x + a1v * k1.x + a2 * k2.x + a3 * k3.x;
        float ry = a0 * k0.y + a1v * k1.y + a2 * k2.y + a3 * k3.y;
        float rz = a0 * k0.z + a1v * k1.z + a2 * k2.z + a3 * k3.z;
        float rw = a0 * k0.w + a1v * k1.w + a2 * k2.w + a3 * k3.w;
        __half2 h[2];
        h[0] = __floats2half2_rn(rx, ry);
        h[1] = __floats2half2_rn(rz, rw);
        *(uint2*)(g_w + (long)b * PER_E + off) = *(uint2*)h;
    }
}

// ---------------------------------------------------------------------------
// 5) Implicit-GEMM conv with mma.sync, register-pipelined fragments.
// ---------------------------------------------------------------------------
__global__ __launch_bounds__(256, 2)
void conv_mma_kernel(float* __restrict__ out) {
    extern __shared__ __align__(1024) char smem[];
    uint32_t sb = smem_u32(smem);
    int tid = threadIdx.x;
    int lane = tid & 31, wid = tid >> 5;
    int wm = wid >> 2, wn = wid & 3;          // 2 x 4 warp grid, warp tile 64x32
    int b = blockIdx.z;
    int m0 = blockIdx.x * BM;
    int n0 = blockIdx.y * BN;

    float acc[4][4][4];
#pragma unroll
    for (int i = 0; i < 4; i++)
#pragma unroll
        for (int j = 0; j < 4; j++)
#pragma unroll
            for (int k = 0; k < 4; k++) acc[i][j][k] = 0.f;

    const long inb = (long)b * HW_ * C_;
    const long wbb = (long)b * (long)KTOT * F_;

    const int a_row = tid >> 1;
    const int a_seg = (tid & 1) * 2;

    auto load_stage = [&](int stage, int kt) {
        uint32_t st = sb + stage * STG_BYTES;
        int r = kt >> 3;
        int cbase = (kt & 7) << 5;
        int ky = r / 3 - 1, kx = r % 3 - 1;
        {
            int m = m0 + a_row;
            int h = m >> 6, w = m & 63;
            int ih = h + ky, iw = w + kx;
            unsigned ok = ((unsigned)ih < H_) & ((unsigned)iw < W_);
            const __half* src = g_in_h + (ok ? (inb + ((long)((ih << 6) + iw)) * C_ + cbase + a_seg * 8) : 0);
            uint32_t d = st + a_row * A_ROW_BYTES + a_seg * 16;
            CP_ASYNC16(d, src, ok);
            CP_ASYNC16(d + 16, src + 8, ok);
        }
#pragma unroll
        for (int i = 0; i < 2; i++) {
            int cid = tid + i * 256;
            int kk = cid >> 4;
            int ch = cid & 15;
            const __half* src = g_w + wbb + ((long)(r * C_ + cbase + kk)) * F_ + n0 + ch * 8;
            uint32_t d = st + A_STAGE + kk * 256 + ((ch ^ (kk & 7)) << 4);
            CP_ASYNC16(d, src, 1u);
        }
    };

#pragma unroll
    for (int s = 0; s < 3; s++) { load_stage(s, s); CP_COMMIT(); }

    // per-warp invariant ldsm addressing
    const int a_lrow = wm * 64 + ((lane >> 3) & 1) * 8 + (lane & 7);
    const int a_ksel = (lane >> 4);
    const int b_klane = ((lane >> 3) & 1) * 8 + (lane & 7);

    uint32_t af[2][4][4];   // [ksbuf][mt][frag]
    uint32_t bf[2][2][4];   // [ksbuf][p][frag]

#define LOAD_FRAGS(buf, ks, stA, stB) do { \
    _Pragma("unroll") \
    for (int mt = 0; mt < 4; mt++) \
        LDSM_X4(af[buf][mt][0], af[buf][mt][1], af[buf][mt][2], af[buf][mt][3], \
                (stA) + (a_lrow + mt * 16) * A_ROW_BYTES + ((ks) * 2 + a_ksel) * 16); \
    _Pragma("unroll") \
    for (int p = 0; p < 2; p++) { \
        int kkl = (ks) * 16 + b_klane; \
        int nch = wn * 4 + p * 2 + (lane >> 4); \
        LDSM_X4_T(bf[buf][p][0], bf[buf][p][1], bf[buf][p][2], bf[buf][p][3], \
                  (stB) + kkl * 256 + ((nch ^ (kkl & 7)) << 4)); \
    } \
} while (0)

#define DO_MMAS(buf) do { \
    _Pragma("unroll") \
    for (int mt = 0; mt < 4; mt++) { \
        _Pragma("unroll") \
        for (int ng = 0; ng < 4; ng++) { \
            uint32_t bb0 = bf[buf][ng >> 1][(ng & 1) * 2]; \
            uint32_t bb1 = bf[buf][ng >> 1][(ng & 1) * 2 + 1]; \
            MMA16816(acc[mt][ng][0], acc[mt][ng][1], acc[mt][ng][2], acc[mt][ng][3], \
                     af[buf][mt][0], af[buf][mt][1], af[buf][mt][2], af[buf][mt][3], bb0, bb1); \
        } \
    } \
} while (0)

    for (int kt = 0; kt < NITER; kt++) {
        CP_WAIT2();
        __syncthreads();

        uint32_t stA = sb + ((kt & 3) * STG_BYTES);
        uint32_t stB = stA + A_STAGE;

        // ks=0 fragments (critical path right after sync)
        LOAD_FRAGS(0, 0, stA, stB);

        // global prefetch for kt+3 (off the frag critical path)
        if (kt + 3 < NITER) load_stage((kt + 3) & 3, kt + 3);
        CP_COMMIT();

        // ks=1 fragments, then MMAs for ks=0 (LDSM latency hidden under MMAs)
        LOAD_FRAGS(1, 1, stA, stB);
        DO_MMAS(0);
        DO_MMAS(1);
    }

    // epilogue: bias + store
    float2 bias[4];
#pragma unroll
    for (int ng = 0; ng < 4; ng++) {
        int col = n0 + wn * 32 + ng * 8 + (lane & 3) * 2;
        bias[ng] = *(const float2*)(g_bias + b * F_ + col);
    }
#pragma unroll
    for (int mt = 0; mt < 4; mt++) {
        int row0 = m0 + wm * 64 + mt * 16 + (lane >> 2);
        float* p0 = out + ((long)b * HW_ + row0) * F_;
        float* p1 = p0 + 8L * F_;
#pragma unroll
        for (int ng = 0; ng < 4; ng++) {
            int col = n0 + wn * 32 + ng * 8 + (lane & 3) * 2;
            float2 v0 = make_float2(acc[mt][ng][0] + bias[ng].x, acc[mt][ng][1] + bias[ng].y);
            float2 v1 = make_float2(acc[mt][ng][2] + bias[ng].x, acc[mt][ng][3] + bias[ng].y);
            *(float2*)(p0 + col) = v0;
            *(float2*)(p1 + col) = v1;
        }
    }
}

// ---------------------------------------------------------------------------
// Launch
// ---------------------------------------------------------------------------
extern "C" void kernel_launch(void* const* d_in, const int* in_sizes, int n_in,
                              void* d_out, int out_size) {
    const float* inputs  = (const float*)d_in[0];
    const float* kernels = (const float*)d_in[1];
    const float* biases  = (const float*)d_in[2];
    const float* w1      = (const float*)d_in[3];
    const float* b1      = (const float*)d_in[4];
    const float* w2      = (const float*)d_in[5];
    const float* b2      = (const float*)d_in[6];
    float* out = (float*)d_out;

    static int smem_set = 0;
    if (!smem_set) {
        cudaFuncSetAttribute(conv_mma_kernel, cudaFuncAttributeMaxDynamicSharedMemorySize, SMEM_TOTAL);
        smem_set = 1;
    }

    pool_kernel<<<dim3(16, B_), 256>>>(inputs);
    route_kernel<<<B_, 256>>>(w1, b1, w2, b2, biases);
    tohalf_kernel<<<(B_ * HW_ * C_) / 8 / 256, 256>>>(inputs);
    combine_h_kernel<<<PER_E / 4 / 256, 256>>>(kernels);
    conv_mma_kernel<<<dim3(HW_ / BM, F_ / BN, B_), 256, SMEM_TOTAL>>>(out);
}